// round 16
// baseline (speedup 1.0000x reference)
#include <cuda_runtime.h>

// transforms_blue: per-pixel BGR2GRAY + conditional channel boost, fp32 in/out.
// Layout [B=64, C=3, H=512, W=512]; channel plane = 512*512 = 262144 floats.
//
// FINAL converged kernel (15 rounds, 9 consecutive confirming profiles).
// HBM-bound at the achieved-DRAM ceiling (~6.2 TB/s, 77% of spec) for this
// 3-read/3-write plane-interleaved fp32 stream — the mixed read/write
// bus-turnaround bound on HBM3e.
//
// Measured landscape: vector width 128b/256b — neutral; per-thread MLP 3/6 —
// neutral; all L2 hint combos — neutral; CTA 128/256 — neutral; persistent
// grids @32/@64 warps/SM — regressed; strided-warp layout — regressed.
// Rejected on model grounds: TMA stores (LTS cap path-independent), smem
// write phasing (uncoordinatable across 1100+ CTAs), MLP=12 (occupancy
// collapse). Logical traffic (403MB) irreducible; L2 absorbs ~15% of writes.
// Kernel floor: 56.3-56.9us across 9 profiles; bench noise band 63.8-64.9us.
//
// Shape: 128 thr/CTA, 1 float4-group/thread, fully coalesced LDG.128/STG.128,
// streaming (evict-first) hints on both zero-reuse streams, exact grid.

#define PLANE   262144          // floats per channel plane (512*512)
#define PLANE4  (PLANE / 4)     // 65536 float4 per plane
#define BATCH_STRIDE (3 * PLANE)
#define NPIX4   (64 * PLANE4)   // 4,194,304 float4 pixel-groups (divides 128)
#define THREADS 128

__device__ __forceinline__ float gray_of(float x0, float x1, float x2) {
    float u0 = floorf(x0 * 255.0f);
    float u1 = floorf(x1 * 255.0f);
    float u2 = floorf(x2 * 255.0f);
    return rintf(0.114f * u0 + 0.587f * u1 + 0.299f * u2);  // jnp.round = half-even
}

__device__ __forceinline__ void px(float a, float b, float c,
                                   float& r0, float& r1, float& r2) {
    const float inv255 = 1.0f / 255.0f;
    float gy = gray_of(a, b, c);
    bool m = gy < 128.0f;
    r0 = (m ? gy + 60.0f : gy) * inv255;
    r1 = (m ? gy + 10.0f : gy) * inv255;
    r2 = gy * inv255;
}

__global__ void __launch_bounds__(THREADS) transforms_blue_kernel(
    const float* __restrict__ in, float* __restrict__ out)
{
    unsigned g = blockIdx.x * THREADS + threadIdx.x;   // exact grid, no check

    unsigned b    = g >> 16;            // g / PLANE4
    unsigned off  = (g & 65535u) * 4;   // float offset within plane
    unsigned base = b * BATCH_STRIDE + off;

    // 3 independent, fully-coalesced, streaming 128-bit loads
    const float4 v0 = __ldcs(reinterpret_cast<const float4*>(in + base));
    const float4 v1 = __ldcs(reinterpret_cast<const float4*>(in + base + PLANE));
    const float4 v2 = __ldcs(reinterpret_cast<const float4*>(in + base + 2 * PLANE));

    float4 o0, o1, o2;
    px(v0.x, v1.x, v2.x, o0.x, o1.x, o2.x);
    px(v0.y, v1.y, v2.y, o0.y, o1.y, o2.y);
    px(v0.z, v1.z, v2.z, o0.z, o1.z, o2.z);
    px(v0.w, v1.w, v2.w, o0.w, o1.w, o2.w);

    __stcs(reinterpret_cast<float4*>(out + base),             o0);
    __stcs(reinterpret_cast<float4*>(out + base + PLANE),     o1);
    __stcs(reinterpret_cast<float4*>(out + base + 2 * PLANE), o2);
}

extern "C" void kernel_launch(void* const* d_in, const int* in_sizes, int n_in,
                              void* d_out, int out_size) {
    const float* in = (const float*)d_in[0];
    float* out = (float*)d_out;
    const int blocks = NPIX4 / THREADS;   // 32768, exact
    transforms_blue_kernel<<<blocks, THREADS>>>(in, out);
}

// round 17
// speedup vs baseline: 1.0095x; 1.0095x over previous
#include <cuda_runtime.h>

// transforms_blue: per-pixel BGR2GRAY + conditional channel boost, fp32 in/out.
// Layout [B=64, C=3, H=512, W=512]; channel plane = 512*512 = 262144 floats.
//
// FINAL converged kernel (16 rounds, 10 consecutive confirming profiles).
// HBM-bound at the achieved-DRAM ceiling (~6.1-6.25 TB/s, 76-78% of spec) for
// this 3-read/3-write plane-interleaved fp32 stream — the mixed read/write
// bus-turnaround bound on HBM3e.
//
// Measured landscape: vector width 128b/256b — neutral; per-thread MLP 3/6 —
// neutral; all L2 hint combos — neutral; CTA 128/256 — neutral; persistent
// grids @32/@64 warps/SM — regressed; strided-warp layout — regressed.
// Rejected on model grounds: TMA stores (LTS cap path-independent), smem
// write phasing (uncoordinatable across 1100+ CTAs), MLP=12 (occupancy
// collapse). Logical traffic (403MB) irreducible; L2 absorbs ~15% of writes.
// Kernel floor: 56.3-57.3us across 10 profiles; bench noise band 63.8-64.9us.
//
// Shape: 128 thr/CTA, 1 float4-group/thread, fully coalesced LDG.128/STG.128,
// streaming (evict-first) hints on both zero-reuse streams, exact grid.

#define PLANE   262144          // floats per channel plane (512*512)
#define PLANE4  (PLANE / 4)     // 65536 float4 per plane
#define BATCH_STRIDE (3 * PLANE)
#define NPIX4   (64 * PLANE4)   // 4,194,304 float4 pixel-groups (divides 128)
#define THREADS 128

__device__ __forceinline__ float gray_of(float x0, float x1, float x2) {
    float u0 = floorf(x0 * 255.0f);
    float u1 = floorf(x1 * 255.0f);
    float u2 = floorf(x2 * 255.0f);
    return rintf(0.114f * u0 + 0.587f * u1 + 0.299f * u2);  // jnp.round = half-even
}

__device__ __forceinline__ void px(float a, float b, float c,
                                   float& r0, float& r1, float& r2) {
    const float inv255 = 1.0f / 255.0f;
    float gy = gray_of(a, b, c);
    bool m = gy < 128.0f;
    r0 = (m ? gy + 60.0f : gy) * inv255;
    r1 = (m ? gy + 10.0f : gy) * inv255;
    r2 = gy * inv255;
}

__global__ void __launch_bounds__(THREADS) transforms_blue_kernel(
    const float* __restrict__ in, float* __restrict__ out)
{
    unsigned g = blockIdx.x * THREADS + threadIdx.x;   // exact grid, no check

    unsigned b    = g >> 16;            // g / PLANE4
    unsigned off  = (g & 65535u) * 4;   // float offset within plane
    unsigned base = b * BATCH_STRIDE + off;

    // 3 independent, fully-coalesced, streaming 128-bit loads
    const float4 v0 = __ldcs(reinterpret_cast<const float4*>(in + base));
    const float4 v1 = __ldcs(reinterpret_cast<const float4*>(in + base + PLANE));
    const float4 v2 = __ldcs(reinterpret_cast<const float4*>(in + base + 2 * PLANE));

    float4 o0, o1, o2;
    px(v0.x, v1.x, v2.x, o0.x, o1.x, o2.x);
    px(v0.y, v1.y, v2.y, o0.y, o1.y, o2.y);
    px(v0.z, v1.z, v2.z, o0.z, o1.z, o2.z);
    px(v0.w, v1.w, v2.w, o0.w, o1.w, o2.w);

    __stcs(reinterpret_cast<float4*>(out + base),             o0);
    __stcs(reinterpret_cast<float4*>(out + base + PLANE),     o1);
    __stcs(reinterpret_cast<float4*>(out + base + 2 * PLANE), o2);
}

extern "C" void kernel_launch(void* const* d_in, const int* in_sizes, int n_in,
                              void* d_out, int out_size) {
    const float* in = (const float*)d_in[0];
    float* out = (float*)d_out;
    const int blocks = NPIX4 / THREADS;   // 32768, exact
    transforms_blue_kernel<<<blocks, THREADS>>>(in, out);
}